// round 16
// baseline (speedup 1.0000x reference)
#include <cuda_runtime.h>
#include <cuda_bf16.h>

#define LOG2E 1.4426950408889634f
#define MAGIC 12582912.0f   // 1.5 * 2^23

typedef unsigned long long u64;

__device__ __forceinline__ u64 pk2(float lo, float hi) {
    u64 r; asm("mov.b64 %0, {%1, %2};" : "=l"(r) : "f"(lo), "f"(hi)); return r;
}
__device__ __forceinline__ u64 dup2c(float v) {
    unsigned bits = __float_as_uint(v);
    return ((u64)bits << 32) | bits;
}
__device__ __forceinline__ u64 ffma2(u64 a, u64 b, u64 c) {
    u64 d; asm("fma.rn.f32x2 %0, %1, %2, %3;" : "=l"(d) : "l"(a), "l"(b), "l"(c)); return d;
}
__device__ __forceinline__ u64 fadd2(u64 a, u64 b) {
    u64 d; asm("add.rn.f32x2 %0, %1, %2;" : "=l"(d) : "l"(a), "l"(b)); return d;
}
__device__ __forceinline__ float sqrt_ap(float x) {
    float d; asm("sqrt.approx.f32 %0, %1;" : "=f"(d) : "f"(x)); return d;
}
__device__ __forceinline__ float ex2_ap(float x) {
    float e; asm("ex2.approx.f32 %0, %1;" : "=f"(e) : "f"(x)); return e;
}
__device__ __forceinline__ float lo_f(u64 v) { return __uint_as_float((unsigned)v); }
__device__ __forceinline__ float hi_f(u64 v) { return __uint_as_float((unsigned)(v >> 32)); }

// Packed squared distance for one atom pair: s = qn + pw - 2 q.p  (both halves)
#define DIST2(PA, PB) \
    ffma2(m2x2, (PA).x, ffma2(m2y2, (PA).y, ffma2(m2z2, (PB).x, fadd2((PB).y, qn2))))

// Packed exp2 (x >= 0): round via MAGIC add, deg-4 Taylor on |f|<=0.5,
// exponent applied with (t_bits << 23) integer add (MAGIC<<23 == 0 mod 2^32).
#define EXP2_PAIR(x, r0, r1) do {                                         \
    u64 t_  = fadd2((x), dup2c(MAGIC));                                   \
    u64 nf_ = fadd2(t_, dup2c(-MAGIC));                                   \
    u64 f_  = ffma2(nf_, dup2c(-1.0f), (x));                              \
    u64 p_  = ffma2(dup2c(0.0096181291076285f), f_, dup2c(0.0555041086648216f)); \
    p_ = ffma2(p_, f_, dup2c(0.2402265069591007f));                       \
    p_ = ffma2(p_, f_, dup2c(0.6931471805599453f));                       \
    p_ = ffma2(p_, f_, dup2c(1.0f));                                      \
    unsigned tl_ = (unsigned)t_, th_ = (unsigned)(t_ >> 32);              \
    unsigned pl_ = (unsigned)p_, ph_ = (unsigned)(p_ >> 32);              \
    r0 = __uint_as_float(pl_ + (tl_ << 23));                              \
    r1 = __uint_as_float(ph_ + (th_ << 23));                              \
} while (0)

#define GPB 64   // grid points per block; 128 threads = 2 atom-halves per g
#define NT  128  // threads per CTA: 16 CTAs/SM resident -> 100% static occ

__global__ __launch_bounds__(NT, 16)
void initlayer_kernel(const float* __restrict__ R,
                      const float* __restrict__ coords,
                      const float* __restrict__ W,
                      float* __restrict__ out,
                      int A, int G) {
    // Pair-packed atoms, 32B per pair:
    //   [2p] .x=(px0,px1) .y=(py0,py1)   [2p+1] .x=(pz0,pz1) .y=(pw0,pw1)
    extern __shared__ float smem[];
    const ulonglong2* smp = (const ulonglong2*)smem;
    float* red = smem + ((A + 1) / 2) * 8;

    const int tid  = threadIdx.x;
    const int b    = blockIdx.y;
    const int gl   = tid & (GPB - 1);
    const int half = tid >> 6;           // 0 or 1: which atom half
    const int g    = blockIdx.x * GPB + gl;

    // Weight pre-scaled by log2(e): exp(||W(c-r)||) == 2^(||W'(c-r)||).
    const float w00 = W[0] * LOG2E, w01 = W[1] * LOG2E, w02 = W[2] * LOG2E;
    const float w10 = W[3] * LOG2E, w11 = W[4] * LOG2E, w12 = W[5] * LOG2E;
    const float w20 = W[6] * LOG2E, w21 = W[7] * LOG2E, w22 = W[8] * LOG2E;

    // Prologue: transform atoms, store pair-packed (p', |p'|^2).
    for (int a = tid; a < A; a += NT) {
        const float* r = R + ((long)b * A + a) * 3;
        float rx = r[0], ry = r[1], rz = r[2];
        float px = fmaf(w00, rx, fmaf(w01, ry, w02 * rz));
        float py = fmaf(w10, rx, fmaf(w11, ry, w12 * rz));
        float pz = fmaf(w20, rx, fmaf(w21, ry, w22 * rz));
        float pw = fmaf(px, px, fmaf(py, py, pz * pz));
        float* base = smem + (a >> 1) * 8;
        int h = a & 1;
        base[0 + h] = px;
        base[2 + h] = py;
        base[4 + h] = pz;
        base[6 + h] = pw;
    }
    __syncthreads();

    float result = 0.0f;
    if (g < G) {
        const float cx = coords[g * 3 + 0];
        const float cy = coords[g * 3 + 1];
        const float cz = coords[g * 3 + 2];
        const float qx = fmaf(w00, cx, fmaf(w01, cy, w02 * cz));
        const float qy = fmaf(w10, cx, fmaf(w11, cy, w12 * cz));
        const float qz = fmaf(w20, cx, fmaf(w21, cy, w22 * cz));
        const float qn = fmaf(qx, qx, fmaf(qy, qy, qz * qz));

        const u64 m2x2 = pk2(-2.0f * qx, -2.0f * qx);
        const u64 m2y2 = pk2(-2.0f * qy, -2.0f * qy);
        const u64 m2z2 = pk2(-2.0f * qz, -2.0f * qz);
        const u64 qn2  = pk2(qn, qn);

        float acc0 = 0.0f, acc1 = 0.0f, acc2 = 0.0f, acc3 = 0.0f;

        if (A == 256) {
            // 128 atoms per thread-half = 64 pairs.
            // Hybrid r=1/2: alternate MUFU-ex2 pair and packed-poly pair
            // (lowest measured cyc/elem across all tested designs).
            const ulonglong2* tp = smp + half * 128;
            #pragma unroll 8
            for (int p = 0; p < 64; p += 2) {
                // ---- MUFU pair ----
                {
                    ulonglong2 PA = tp[2 * p + 0], PB = tp[2 * p + 1];
                    u64 u = DIST2(PA, PB);
                    acc0 += ex2_ap(sqrt_ap(fabsf(lo_f(u))));
                    acc1 += ex2_ap(sqrt_ap(fabsf(hi_f(u))));
                }
                // ---- poly pair ----
                {
                    ulonglong2 PA = tp[2 * p + 2], PB = tp[2 * p + 3];
                    u64 u = DIST2(PA, PB);
                    float d0 = sqrt_ap(fabsf(lo_f(u)));
                    float d1 = sqrt_ap(fabsf(hi_f(u)));
                    u64 x = pk2(d0, d1);
                    float r0, r1;
                    EXP2_PAIR(x, r0, r1);
                    acc2 += r0;
                    acc3 += r1;
                }
            }
        } else {
            // Generic path (MUFU ex2; correctness fallback).
            const int ahalf = A >> 1;
            const int a0 = half ? ahalf : 0;
            const int a1 = half ? A : ahalf;
            const int p0 = (a0 + 1) >> 1;
            const int p1 = a1 >> 1;
            for (int p = p0; p < p1; ++p) {
                ulonglong2 PA = smp[2 * p + 0], PB = smp[2 * p + 1];
                u64 u = DIST2(PA, PB);
                acc0 += ex2_ap(sqrt_ap(fabsf(lo_f(u))));
                acc1 += ex2_ap(sqrt_ap(fabsf(hi_f(u))));
            }
            for (int a = a0; a < 2 * p0 && a < a1; ++a) {
                const float* base = smem + (a >> 1) * 8;
                int h = a & 1;
                float s = fmaf(-2.0f * qx, base[0 + h],
                          fmaf(-2.0f * qy, base[2 + h],
                          fmaf(-2.0f * qz, base[4 + h], qn + base[6 + h])));
                acc0 += ex2_ap(sqrt_ap(fabsf(s)));
            }
            for (int a = (2 * p1 > a0 ? 2 * p1 : a0); a < a1; ++a) {
                const float* base = smem + (a >> 1) * 8;
                int h = a & 1;
                float s = fmaf(-2.0f * qx, base[0 + h],
                          fmaf(-2.0f * qy, base[2 + h],
                          fmaf(-2.0f * qz, base[4 + h], qn + base[6 + h])));
                acc0 += ex2_ap(sqrt_ap(fabsf(s)));
            }
        }
        result = (acc0 + acc1) + (acc2 + acc3);
    }

    // Combine the two atom-half partials; single writer per g.
    if (half == 1) red[gl] = result;
    __syncthreads();
    if (half == 0 && g < G) {
        out[(long)b * G + g] = result + red[gl];
    }
}

extern "C" void kernel_launch(void* const* d_in, const int* in_sizes, int n_in,
                              void* d_out, int out_size) {
    const float* R      = (const float*)d_in[0];  // (B, A, 3) f32
    const float* coords = (const float*)d_in[1];  // (G, 3)    f32
    const float* W      = (const float*)d_in[2];  // (3, 3)    f32

    const int A = in_sizes[3];
    const int B = in_sizes[0] / (3 * A);
    const int G = in_sizes[1] / 3;

    float* out = (float*)d_out;  // (B, G) f32

    dim3 grid((G + GPB - 1) / GPB, B);
    size_t smem = (size_t)((A + 1) / 2) * 8 * sizeof(float) + GPB * sizeof(float);

    initlayer_kernel<<<grid, NT, smem>>>(R, coords, W, out, A, G);
}

// round 17
// speedup vs baseline: 1.0890x; 1.0890x over previous
#include <cuda_runtime.h>
#include <cuda_bf16.h>

#define LOG2E 1.4426950408889634f
#define MAGIC 12582912.0f   // 1.5 * 2^23

typedef unsigned long long u64;

__device__ __forceinline__ u64 pk2(float lo, float hi) {
    u64 r; asm("mov.b64 %0, {%1, %2};" : "=l"(r) : "f"(lo), "f"(hi)); return r;
}
__device__ __forceinline__ u64 dup2c(float v) {
    unsigned bits = __float_as_uint(v);
    return ((u64)bits << 32) | bits;
}
__device__ __forceinline__ u64 ffma2(u64 a, u64 b, u64 c) {
    u64 d; asm("fma.rn.f32x2 %0, %1, %2, %3;" : "=l"(d) : "l"(a), "l"(b), "l"(c)); return d;
}
__device__ __forceinline__ u64 fadd2(u64 a, u64 b) {
    u64 d; asm("add.rn.f32x2 %0, %1, %2;" : "=l"(d) : "l"(a), "l"(b)); return d;
}
__device__ __forceinline__ float sqrt_ap(float x) {
    float d; asm("sqrt.approx.f32 %0, %1;" : "=f"(d) : "f"(x)); return d;
}
__device__ __forceinline__ float ex2_ap(float x) {
    float e; asm("ex2.approx.f32 %0, %1;" : "=f"(e) : "f"(x)); return e;
}
__device__ __forceinline__ float lo_f(u64 v) { return __uint_as_float((unsigned)v); }
__device__ __forceinline__ float hi_f(u64 v) { return __uint_as_float((unsigned)(v >> 32)); }

__device__ __forceinline__ u64 dist2(ulonglong2 PA, ulonglong2 PB,
                                     u64 m2x, u64 m2y, u64 m2z, u64 qn2) {
    return ffma2(m2x, PA.x, ffma2(m2y, PA.y, ffma2(m2z, PB.x, fadd2(PB.y, qn2))));
}

// Packed exp2 (x >= 0): round via MAGIC add, deg-4 Taylor on |f|<=0.5,
// exponent applied with (t_bits << 23) integer add (MAGIC<<23 == 0 mod 2^32).
#define EXP2_PAIR(x, r0, r1) do {                                         \
    u64 t_  = fadd2((x), dup2c(MAGIC));                                   \
    u64 nf_ = fadd2(t_, dup2c(-MAGIC));                                   \
    u64 f_  = ffma2(nf_, dup2c(-1.0f), (x));                              \
    u64 p_  = ffma2(dup2c(0.0096181291076285f), f_, dup2c(0.0555041086648216f)); \
    p_ = ffma2(p_, f_, dup2c(0.2402265069591007f));                       \
    p_ = ffma2(p_, f_, dup2c(0.6931471805599453f));                       \
    p_ = ffma2(p_, f_, dup2c(1.0f));                                      \
    unsigned tl_ = (unsigned)t_, th_ = (unsigned)(t_ >> 32);              \
    unsigned pl_ = (unsigned)p_, ph_ = (unsigned)(p_ >> 32);              \
    r0 = __uint_as_float(pl_ + (tl_ << 23));                              \
    r1 = __uint_as_float(ph_ + (th_ << 23));                              \
} while (0)

#define NT  128  // threads per CTA
#define GPB 128  // grid points per CTA: 64 g-slots x 2 g per thread

__global__ __launch_bounds__(NT, 10)
void initlayer_kernel(const float* __restrict__ R,
                      const float* __restrict__ coords,
                      const float* __restrict__ W,
                      float* __restrict__ out,
                      int A, int G) {
    // Pair-packed atoms, 32B per pair:
    //   [2p] .x=(px0,px1) .y=(py0,py1)   [2p+1] .x=(pz0,pz1) .y=(pw0,pw1)
    extern __shared__ float smem[];
    const ulonglong2* smp = (const ulonglong2*)smem;
    float* red = smem + ((A + 1) / 2) * 8;   // GPB floats

    const int tid  = threadIdx.x;
    const int b    = blockIdx.y;
    const int gl   = tid & 63;           // g-slot within block
    const int half = tid >> 6;           // atom half
    const int g0   = blockIdx.x * GPB + gl;
    const int g1   = g0 + 64;

    // Weight pre-scaled by log2(e): exp(||W(c-r)||) == 2^(||W'(c-r)||).
    const float w00 = W[0] * LOG2E, w01 = W[1] * LOG2E, w02 = W[2] * LOG2E;
    const float w10 = W[3] * LOG2E, w11 = W[4] * LOG2E, w12 = W[5] * LOG2E;
    const float w20 = W[6] * LOG2E, w21 = W[7] * LOG2E, w22 = W[8] * LOG2E;

    // Prologue: transform atoms, store pair-packed (p', |p'|^2).
    for (int a = tid; a < A; a += NT) {
        const float* r = R + ((long)b * A + a) * 3;
        float rx = r[0], ry = r[1], rz = r[2];
        float px = fmaf(w00, rx, fmaf(w01, ry, w02 * rz));
        float py = fmaf(w10, rx, fmaf(w11, ry, w12 * rz));
        float pz = fmaf(w20, rx, fmaf(w21, ry, w22 * rz));
        float pw = fmaf(px, px, fmaf(py, py, pz * pz));
        float* base = smem + (a >> 1) * 8;
        int h = a & 1;
        base[0 + h] = px;
        base[2 + h] = py;
        base[4 + h] = pz;
        base[6 + h] = pw;
    }
    __syncthreads();

    // q' for both grid points (clamped loads; stores guarded below).
    const int gc0 = g0 < G ? g0 : G - 1;
    const int gc1 = g1 < G ? g1 : G - 1;
    float cx0 = coords[gc0 * 3 + 0], cy0 = coords[gc0 * 3 + 1], cz0 = coords[gc0 * 3 + 2];
    float cx1 = coords[gc1 * 3 + 0], cy1 = coords[gc1 * 3 + 1], cz1 = coords[gc1 * 3 + 2];

    float qx0 = fmaf(w00, cx0, fmaf(w01, cy0, w02 * cz0));
    float qy0 = fmaf(w10, cx0, fmaf(w11, cy0, w12 * cz0));
    float qz0 = fmaf(w20, cx0, fmaf(w21, cy0, w22 * cz0));
    float qn0 = fmaf(qx0, qx0, fmaf(qy0, qy0, qz0 * qz0));
    float qx1 = fmaf(w00, cx1, fmaf(w01, cy1, w02 * cz1));
    float qy1 = fmaf(w10, cx1, fmaf(w11, cy1, w12 * cz1));
    float qz1 = fmaf(w20, cx1, fmaf(w21, cy1, w22 * cz1));
    float qn1 = fmaf(qx1, qx1, fmaf(qy1, qy1, qz1 * qz1));

    const u64 m2x0 = pk2(-2.0f * qx0, -2.0f * qx0);
    const u64 m2y0 = pk2(-2.0f * qy0, -2.0f * qy0);
    const u64 m2z0 = pk2(-2.0f * qz0, -2.0f * qz0);
    const u64 qn20 = pk2(qn0, qn0);
    const u64 m2x1 = pk2(-2.0f * qx1, -2.0f * qx1);
    const u64 m2y1 = pk2(-2.0f * qy1, -2.0f * qy1);
    const u64 m2z1 = pk2(-2.0f * qz1, -2.0f * qz1);
    const u64 qn21 = pk2(qn1, qn1);

    float a0 = 0.0f, a1 = 0.0f, a2 = 0.0f, a3 = 0.0f;   // g0 accs
    float b0 = 0.0f, b1 = 0.0f, b2 = 0.0f, b3 = 0.0f;   // g1 accs

    if (A == 256) {
        // 128 atoms per half = 64 pairs. Each pair's LDS serves BOTH g's
        // (halved LDS traffic, halved loop overhead, 2x per-thread ILP).
        // Hybrid exp: even pairs MUFU ex2, odd pairs packed-poly exp2.
        const ulonglong2* tp = smp + half * 128;
        #pragma unroll 4
        for (int p = 0; p < 64; p += 2) {
            // ---- MUFU pair (both g) ----
            {
                ulonglong2 PA = tp[2 * p + 0], PB = tp[2 * p + 1];
                u64 u0 = dist2(PA, PB, m2x0, m2y0, m2z0, qn20);
                u64 u1 = dist2(PA, PB, m2x1, m2y1, m2z1, qn21);
                a0 += ex2_ap(sqrt_ap(fabsf(lo_f(u0))));
                a1 += ex2_ap(sqrt_ap(fabsf(hi_f(u0))));
                b0 += ex2_ap(sqrt_ap(fabsf(lo_f(u1))));
                b1 += ex2_ap(sqrt_ap(fabsf(hi_f(u1))));
            }
            // ---- poly pair (both g) ----
            {
                ulonglong2 PA = tp[2 * p + 2], PB = tp[2 * p + 3];
                u64 u0 = dist2(PA, PB, m2x0, m2y0, m2z0, qn20);
                u64 u1 = dist2(PA, PB, m2x1, m2y1, m2z1, qn21);
                u64 x0 = pk2(sqrt_ap(fabsf(lo_f(u0))), sqrt_ap(fabsf(hi_f(u0))));
                u64 x1 = pk2(sqrt_ap(fabsf(lo_f(u1))), sqrt_ap(fabsf(hi_f(u1))));
                float r0, r1, r2, r3;
                EXP2_PAIR(x0, r0, r1);
                EXP2_PAIR(x1, r2, r3);
                a2 += r0; a3 += r1;
                b2 += r2; b3 += r3;
            }
        }
    } else {
        // Generic fallback: MUFU path, per-g loop over this half's atoms.
        const int ahalf = A >> 1;
        const int as = half ? ahalf : 0;
        const int ae = half ? A : ahalf;
        for (int a = as; a < ae; ++a) {
            const float* base = smem + (a >> 1) * 8;
            int h = a & 1;
            float px = base[0 + h], py = base[2 + h], pz = base[4 + h], pw = base[6 + h];
            float s0 = fmaf(-2.0f * qx0, px, fmaf(-2.0f * qy0, py,
                       fmaf(-2.0f * qz0, pz, qn0 + pw)));
            float s1 = fmaf(-2.0f * qx1, px, fmaf(-2.0f * qy1, py,
                       fmaf(-2.0f * qz1, pz, qn1 + pw)));
            a0 += ex2_ap(sqrt_ap(fabsf(s0)));
            b0 += ex2_ap(sqrt_ap(fabsf(s1)));
        }
    }

    float res0 = (a0 + a1) + (a2 + a3);
    float res1 = (b0 + b1) + (b2 + b3);

    // Combine the two atom-half partials; single writer per g.
    if (half == 1) {
        red[gl]      = res0;
        red[gl + 64] = res1;
    }
    __syncthreads();
    if (half == 0) {
        if (g0 < G) out[(long)b * G + g0] = res0 + red[gl];
        if (g1 < G) out[(long)b * G + g1] = res1 + red[gl + 64];
    }
}

extern "C" void kernel_launch(void* const* d_in, const int* in_sizes, int n_in,
                              void* d_out, int out_size) {
    const float* R      = (const float*)d_in[0];  // (B, A, 3) f32
    const float* coords = (const float*)d_in[1];  // (G, 3)    f32
    const float* W      = (const float*)d_in[2];  // (3, 3)    f32

    const int A = in_sizes[3];
    const int B = in_sizes[0] / (3 * A);
    const int G = in_sizes[1] / 3;

    float* out = (float*)d_out;  // (B, G) f32

    dim3 grid((G + GPB - 1) / GPB, B);
    size_t smem = (size_t)((A + 1) / 2) * 8 * sizeof(float) + GPB * sizeof(float);

    initlayer_kernel<<<grid, NT, smem>>>(R, coords, W, out, A, G);
}